// round 13
// baseline (speedup 1.0000x reference)
#include <cuda_runtime.h>
#include <cuda_fp16.h>
#include <cstdint>

#define EPS         1e-8f
#define NT          512
#define C_DIM       32000
#define CHUNK_F4    2000                 // float4 per chunk
#define CHUNK_F     8000                 // floats per chunk
#define CHUNK_BYTES 32000                // 2000 * 16
#define NBUF        3
#define GRID        304                  // 2 CTAs per SM x 152 SMs
#define LOG2E       1.4426950408889634f

__device__ int g_ctr;                    // dynamic row queue head

__global__ void init_ctr_kernel() { g_ctr = GRID; }

__device__ __forceinline__ unsigned int smem_u32(const void* p) {
    return (unsigned int)__cvta_generic_to_shared(p);
}

__device__ __forceinline__ void mbar_wait(unsigned int mb, unsigned int parity) {
    asm volatile(
        "{\n\t"
        ".reg .pred P;\n\t"
        "WAIT_%=:\n\t"
        "mbarrier.try_wait.parity.acquire.cta.shared::cta.b64 P, [%0], %1, 0x989680;\n\t"
        "@P bra DONE_%=;\n\t"
        "bra WAIT_%=;\n\t"
        "DONE_%=:\n\t"
        "}"
        :: "r"(mb), "r"(parity) : "memory");
}

__device__ __forceinline__ void mbar_arrive(unsigned int mb) {
    asm volatile("mbarrier.arrive.release.cta.shared::cta.b64 _, [%0];"
                 :: "r"(mb) : "memory");
}

__device__ __forceinline__ void tma_issue(unsigned int mb, unsigned int dst,
                                          const float* src) {
    asm volatile("mbarrier.arrive.expect_tx.shared.b64 _, [%0], %1;"
                 :: "r"(mb), "r"((unsigned int)CHUNK_BYTES) : "memory");
    asm volatile("cp.async.bulk.shared::cluster.global.mbarrier::complete_tx::bytes "
                 "[%0], [%1], %2, [%3];"
                 :: "r"(dst), "l"(src), "r"((unsigned int)CHUNK_BYTES), "r"(mb)
                 : "memory");
}

// exp(x + EPS) = exp2(x*log2e + EPS*log2e): one FFMA + one MUFU.EX2
__device__ __forceinline__ float expe(float x) {
    return exp2f(fmaf(x, LOG2E, EPS * LOG2E));
}

__global__ __launch_bounds__(NT, 2)
void smsoftmax_kernel(const float* __restrict__ logits,
                      const float* __restrict__ dist,
                      float* __restrict__ out, int B) {
    extern __shared__ float4 buf[];              // NBUF x CHUNK_F4 float4 = 96000 B
    __shared__ __align__(8) unsigned long long mbar_full[NBUF];
    __shared__ __align__(8) unsigned long long mbar_empty[NBUF];
    __shared__ float red[2][16];                 // double-buffered by row parity
    __shared__ int   sh_next[2];

    const int tid  = threadIdx.x;
    const int lane = tid & 31;
    const int wid  = tid >> 5;

    const unsigned int fb_base  = smem_u32(&mbar_full[0]);   // +8*i
    const unsigned int eb_base  = smem_u32(&mbar_empty[0]);  // +8*i
    const unsigned int dst_base = smem_u32(buf);             // +i*CHUNK_BYTES

    if (tid == 0) {
        #pragma unroll
        for (int i = 0; i < NBUF; i++) {
            asm volatile("mbarrier.init.shared.b64 [%0], 1;"
                         :: "r"(fb_base + 8u * i) : "memory");
            asm volatile("mbarrier.init.shared.b64 [%0], %1;"
                         :: "r"(eb_base + 8u * i), "r"(NT) : "memory");
        }
    }
    __syncthreads();

    int cur = blockIdx.x;                        // static seed: rows 0..GRID-1

    // Prologue: prime the 3 buffers with chunks 0,1,2 of cur (no empty-wait).
    if (tid == 0 && cur < B) {
        const float* base = logits + (size_t)cur * C_DIM;
        #pragma unroll
        for (int i = 0; i < NBUF; i++)
            tma_issue(fb_base + 8u * i, dst_base + (unsigned int)i * CHUNK_BYTES,
                      base + (size_t)i * CHUNK_F);
    }

    const float c   = __expf(-__ldg(dist));
    const float cm1 = c - 1.0f;

    unsigned int pmask = 0;                      // full-barrier parity (all threads)
    unsigned int emask = 0;                      // empty-barrier parity (tid0 only)
    int sb = 0;                                  // starting buffer of current row
    int rp = 0;                                  // row parity for red/sh_next slots

    __half2 eh[32];                              // fp16 e for one full row (regs)

    while (cur < B) {
        float s = 0.0f;
        int nxt = B;

        #pragma unroll
        for (int cslot = 0; cslot < 4; cslot++) {
            int b = sb + cslot;                  // runtime buffer index, 0..2
            if (b >= NBUF) b -= NBUF;
            const unsigned int fba = fb_base + 8u * (unsigned int)b;
            const unsigned int eba = eb_base + 8u * (unsigned int)b;

            mbar_wait(fba, (pmask >> b) & 1u);
            pmask ^= (1u << b);

            const float4* __restrict__ cb = buf + b * CHUNK_F4;
            #pragma unroll
            for (int j = 0; j < 4; j++) {
                int idx = j * NT + tid;
                if (idx < CHUNK_F4) {
                    float4 t = cb[idx];
                    float ex = expe(t.x), ey = expe(t.y);
                    float ez = expe(t.z), ew = expe(t.w);
                    s += (ex + ey) + (ez + ew);
                    eh[(cslot * 4 + j) * 2]     = __floats2half2_rn(ex, ey);
                    eh[(cslot * 4 + j) * 2 + 1] = __floats2half2_rn(ez, ew);
                }
            }
            // per-thread consumer release: my reads of buffer b are done
            mbar_arrive(eba);

            if (tid == 0) {
                if (cslot == 0) {
                    nxt = atomicAdd(&g_ctr, 1);  // latency hidden by later drains
                    sh_next[rp] = nxt;
                }
                // refill same buffer with chunk q+3:
                //   cslot0 -> chunk3 of cur; cslots1,2,3 -> chunks 0,1,2 of nxt
                const int trow = (cslot == 0) ? cur : nxt;
                const int tch  = (cslot + 3) & 3;
                if (trow < B) {
                    mbar_wait(eba, (emask >> b) & 1u);   // all 512 drained b
                    emask ^= (1u << b);
                    const float* src = logits + (size_t)trow * C_DIM
                                              + (size_t)tch * CHUNK_F;
                    tma_issue(fba, dst_base + (unsigned int)b * CHUNK_BYTES, src);
                }
            }
        }
        sb += 1;                                 // 4 chunks advance start by 4%3 = 1
        if (sb >= NBUF) sb -= NBUF;

        // ---- reduce: warp partials -> ONE barrier -> redundant final fold ----
        float rr = s;
        #pragma unroll
        for (int o = 16; o > 0; o >>= 1)
            rr += __shfl_xor_sync(0xffffffffu, rr, o);
        if (lane == 0) red[rp][wid] = rr;
        __syncthreads();                         // the only block barrier per row

        float t = red[rp][lane & 15];            // every warp folds all 16 partials
        #pragma unroll
        for (int o = 8; o > 0; o >>= 1)
            t += __shfl_xor_sync(0xffffffffu, t, o);

        const int nxtrow = sh_next[rp];          // ordered by the barrier above

        // Per-row scalars: r0 = 1/(s+EPS); out = (c*r0*e) * (1 - cm1*r0*e)
        const float r0 = __fdividef(1.0f, t + EPS);
        const float a  = c * r0;
        const float bb = cm1 * r0;

        // ---- epilogue: pure FMA + STG (overlaps in-flight next-row chunks) ----
        float4* __restrict__ out4 = (float4*)(out + (size_t)cur * C_DIM);
        #pragma unroll
        for (int cs = 0; cs < 4; cs++) {
            #pragma unroll
            for (int j = 0; j < 4; j++) {
                int idx = j * NT + tid;
                if (idx < CHUNK_F4) {
                    float2 lo = __half22float2(eh[(cs * 4 + j) * 2]);
                    float2 hi = __half22float2(eh[(cs * 4 + j) * 2 + 1]);
                    float4 o;
                    o.x = (a * lo.x) * fmaf(-bb, lo.x, 1.0f);
                    o.y = (a * lo.y) * fmaf(-bb, lo.y, 1.0f);
                    o.z = (a * hi.x) * fmaf(-bb, hi.x, 1.0f);
                    o.w = (a * hi.y) * fmaf(-bb, hi.y, 1.0f);
                    out4[cs * CHUNK_F4 + idx] = o;
                }
            }
        }

        cur = nxtrow;
        rp ^= 1;                                 // flip red/sh_next slot
    }
}

extern "C" void kernel_launch(void* const* d_in, const int* in_sizes, int n_in,
                              void* d_out, int out_size) {
    const float* logits = (const float*)d_in[0];
    const float* dist   = (const float*)d_in[1];
    float* out = (float*)d_out;

    const int B = in_sizes[0] / C_DIM;                 // 4096 rows
    const size_t smem = (size_t)NBUF * CHUNK_BYTES;    // 96000 B per CTA

    init_ctr_kernel<<<1, 1>>>();                       // reset queue head each launch
    cudaFuncSetAttribute(smsoftmax_kernel,
                         cudaFuncAttributeMaxDynamicSharedMemorySize, (int)smem);
    smsoftmax_kernel<<<GRID, NT, smem>>>(logits, dist, out, B);
}

// round 14
// speedup vs baseline: 1.0041x; 1.0041x over previous
#include <cuda_runtime.h>
#include <cuda_fp16.h>
#include <cstdint>

#define EPS         1e-8f
#define NT          512
#define C_DIM       32000
#define CHUNK_F4    2000                 // float4 per chunk
#define CHUNK_F     8000                 // floats per chunk
#define CHUNK_BYTES 32000                // 2000 * 16
#define NBUF        3
#define GRID        304                  // 2 CTAs per SM x 152 SMs
#define LOG2E       1.4426950408889634f

// Self-resetting work queue: statically initialized; the LAST exiting CTA of
// each launch restores {g_ctr=GRID, g_done=0} for the next launch. Every CTA's
// final g_ctr use precedes its g_done increment, so the reset is race-free,
// and launch-boundary ordering publishes it to the next graph replay.
__device__ int g_ctr  = GRID;
__device__ int g_done = 0;

__device__ __forceinline__ unsigned int smem_u32(const void* p) {
    return (unsigned int)__cvta_generic_to_shared(p);
}

__device__ __forceinline__ void mbar_wait(unsigned int mb, unsigned int parity) {
    asm volatile(
        "{\n\t"
        ".reg .pred P;\n\t"
        "WAIT_%=:\n\t"
        "mbarrier.try_wait.parity.acquire.cta.shared::cta.b64 P, [%0], %1, 0x989680;\n\t"
        "@P bra DONE_%=;\n\t"
        "bra WAIT_%=;\n\t"
        "DONE_%=:\n\t"
        "}"
        :: "r"(mb), "r"(parity) : "memory");
}

__device__ __forceinline__ void mbar_arrive(unsigned int mb) {
    asm volatile("mbarrier.arrive.release.cta.shared::cta.b64 _, [%0];"
                 :: "r"(mb) : "memory");
}

__device__ __forceinline__ void tma_issue(unsigned int mb, unsigned int dst,
                                          const float* src) {
    asm volatile("mbarrier.arrive.expect_tx.shared.b64 _, [%0], %1;"
                 :: "r"(mb), "r"((unsigned int)CHUNK_BYTES) : "memory");
    asm volatile("cp.async.bulk.shared::cluster.global.mbarrier::complete_tx::bytes "
                 "[%0], [%1], %2, [%3];"
                 :: "r"(dst), "l"(src), "r"((unsigned int)CHUNK_BYTES), "r"(mb)
                 : "memory");
}

// exp(x + EPS) = exp2(x*log2e + EPS*log2e): one FFMA + one MUFU.EX2
__device__ __forceinline__ float expe(float x) {
    return exp2f(fmaf(x, LOG2E, EPS * LOG2E));
}

__global__ __launch_bounds__(NT, 2)
void smsoftmax_kernel(const float* __restrict__ logits,
                      const float* __restrict__ dist,
                      float* __restrict__ out, int B) {
    extern __shared__ float4 buf[];              // NBUF x CHUNK_F4 float4 = 96000 B
    __shared__ __align__(8) unsigned long long mbar_full[NBUF];
    __shared__ __align__(8) unsigned long long mbar_empty[NBUF];
    __shared__ float red[2][16];                 // double-buffered by row parity
    __shared__ int   sh_next[2];

    const int tid  = threadIdx.x;
    const int lane = tid & 31;
    const int wid  = tid >> 5;

    const unsigned int fb_base  = smem_u32(&mbar_full[0]);   // +8*i
    const unsigned int eb_base  = smem_u32(&mbar_empty[0]);  // +8*i
    const unsigned int dst_base = smem_u32(buf);             // +i*CHUNK_BYTES

    if (tid == 0) {
        #pragma unroll
        for (int i = 0; i < NBUF; i++) {
            asm volatile("mbarrier.init.shared.b64 [%0], 1;"
                         :: "r"(fb_base + 8u * i) : "memory");
            asm volatile("mbarrier.init.shared.b64 [%0], %1;"
                         :: "r"(eb_base + 8u * i), "r"(NT) : "memory");
        }
    }
    __syncthreads();

    int cur = blockIdx.x;                        // static seed: rows 0..GRID-1

    // Prologue: prime the 3 buffers with chunks 0,1,2 of cur (no empty-wait).
    if (tid == 0 && cur < B) {
        const float* base = logits + (size_t)cur * C_DIM;
        #pragma unroll
        for (int i = 0; i < NBUF; i++)
            tma_issue(fb_base + 8u * i, dst_base + (unsigned int)i * CHUNK_BYTES,
                      base + (size_t)i * CHUNK_F);
    }

    const float c   = __expf(-__ldg(dist));
    const float cm1 = c - 1.0f;

    unsigned int pmask = 0;                      // full-barrier parity (all threads)
    unsigned int emask = 0;                      // empty-barrier parity (tid0 only)
    int sb = 0;                                  // starting buffer of current row
    int rp = 0;                                  // row parity for red/sh_next slots

    __half2 eh[32];                              // fp16 e for one full row (regs)

    while (cur < B) {
        float s = 0.0f;
        int nxt = B;

        #pragma unroll
        for (int cslot = 0; cslot < 4; cslot++) {
            int b = sb + cslot;                  // runtime buffer index, 0..2
            if (b >= NBUF) b -= NBUF;
            const unsigned int fba = fb_base + 8u * (unsigned int)b;
            const unsigned int eba = eb_base + 8u * (unsigned int)b;

            mbar_wait(fba, (pmask >> b) & 1u);
            pmask ^= (1u << b);

            const float4* __restrict__ cb = buf + b * CHUNK_F4;
            #pragma unroll
            for (int j = 0; j < 4; j++) {
                int idx = j * NT + tid;
                if (idx < CHUNK_F4) {
                    float4 t = cb[idx];
                    float ex = expe(t.x), ey = expe(t.y);
                    float ez = expe(t.z), ew = expe(t.w);
                    s += (ex + ey) + (ez + ew);
                    eh[(cslot * 4 + j) * 2]     = __floats2half2_rn(ex, ey);
                    eh[(cslot * 4 + j) * 2 + 1] = __floats2half2_rn(ez, ew);
                }
            }
            // per-thread consumer release: my reads of buffer b are done
            mbar_arrive(eba);

            if (tid == 0) {
                if (cslot == 0) {
                    nxt = atomicAdd(&g_ctr, 1);  // latency hidden by later drains
                    sh_next[rp] = nxt;
                }
                // refill same buffer with chunk q+3:
                //   cslot0 -> chunk3 of cur; cslots1,2,3 -> chunks 0,1,2 of nxt
                const int trow = (cslot == 0) ? cur : nxt;
                const int tch  = (cslot + 3) & 3;
                if (trow < B) {
                    mbar_wait(eba, (emask >> b) & 1u);   // all 512 drained b
                    emask ^= (1u << b);
                    const float* src = logits + (size_t)trow * C_DIM
                                              + (size_t)tch * CHUNK_F;
                    tma_issue(fba, dst_base + (unsigned int)b * CHUNK_BYTES, src);
                }
            }
        }
        sb += 1;                                 // 4 chunks advance start by 4%3 = 1
        if (sb >= NBUF) sb -= NBUF;

        // ---- reduce: warp partials -> ONE barrier -> redundant final fold ----
        float rr = s;
        #pragma unroll
        for (int o = 16; o > 0; o >>= 1)
            rr += __shfl_xor_sync(0xffffffffu, rr, o);
        if (lane == 0) red[rp][wid] = rr;
        __syncthreads();                         // the only block barrier per row

        float t = red[rp][lane & 15];            // every warp folds all 16 partials
        #pragma unroll
        for (int o = 8; o > 0; o >>= 1)
            t += __shfl_xor_sync(0xffffffffu, t, o);

        const int nxtrow = sh_next[rp];          // ordered by the barrier above

        // Per-row scalars: r0 = 1/(s+EPS); out = (c*r0*e) * (1 - cm1*r0*e)
        const float r0 = __fdividef(1.0f, t + EPS);
        const float a  = c * r0;
        const float bb = cm1 * r0;

        // ---- epilogue: pure FMA + STG (overlaps in-flight next-row chunks) ----
        float4* __restrict__ out4 = (float4*)(out + (size_t)cur * C_DIM);
        #pragma unroll
        for (int cs = 0; cs < 4; cs++) {
            #pragma unroll
            for (int j = 0; j < 4; j++) {
                int idx = j * NT + tid;
                if (idx < CHUNK_F4) {
                    float2 lo = __half22float2(eh[(cs * 4 + j) * 2]);
                    float2 hi = __half22float2(eh[(cs * 4 + j) * 2 + 1]);
                    float4 o;
                    o.x = (a * lo.x) * fmaf(-bb, lo.x, 1.0f);
                    o.y = (a * lo.y) * fmaf(-bb, lo.y, 1.0f);
                    o.z = (a * hi.x) * fmaf(-bb, hi.x, 1.0f);
                    o.w = (a * hi.y) * fmaf(-bb, hi.y, 1.0f);
                    out4[cs * CHUNK_F4 + idx] = o;
                }
            }
        }

        cur = nxtrow;
        rp ^= 1;                                 // flip red/sh_next slot
    }

    // ---- self-reset for the next launch: last CTA out restores the queue ----
    __syncthreads();                             // all this CTA's g_ctr use is done
    if (tid == 0) {
        const int d = atomicAdd(&g_done, 1);
        if (d == GRID - 1) {                     // I am the last CTA to exit
            atomicExch(&g_ctr, GRID);
            atomicExch(&g_done, 0);
        }
    }
}

extern "C" void kernel_launch(void* const* d_in, const int* in_sizes, int n_in,
                              void* d_out, int out_size) {
    const float* logits = (const float*)d_in[0];
    const float* dist   = (const float*)d_in[1];
    float* out = (float*)d_out;

    const int B = in_sizes[0] / C_DIM;                 // 4096 rows
    const size_t smem = (size_t)NBUF * CHUNK_BYTES;    // 96000 B per CTA

    cudaFuncSetAttribute(smsoftmax_kernel,
                         cudaFuncAttributeMaxDynamicSharedMemorySize, (int)smem);
    smsoftmax_kernel<<<GRID, NT, smem>>>(logits, dist, out, B);
}

// round 15
// speedup vs baseline: 1.0075x; 1.0035x over previous
#include <cuda_runtime.h>
#include <cuda_fp16.h>
#include <cstdint>

#define EPS         1e-8f
#define NT          512
#define C_DIM       32000
#define CHUNK_F4    1000                 // float4 per chunk (16 KB)
#define CHUNK_F     4000                 // floats per chunk
#define CHUNK_BYTES 16000
#define NBUF        6                    // 6 x 16 KB = 96 KB (same as before)
#define NCH         8                    // chunks per row
#define GRID        304                  // 2 CTAs per SM x 152 SMs
#define LOG2E       1.4426950408889634f

// Self-resetting work queue (single-node graph): last exiting CTA restores it.
__device__ int g_ctr  = GRID;
__device__ int g_done = 0;

__device__ __forceinline__ unsigned int smem_u32(const void* p) {
    return (unsigned int)__cvta_generic_to_shared(p);
}

__device__ __forceinline__ void mbar_wait(unsigned int mb, unsigned int parity) {
    asm volatile(
        "{\n\t"
        ".reg .pred P;\n\t"
        "WAIT_%=:\n\t"
        "mbarrier.try_wait.parity.acquire.cta.shared::cta.b64 P, [%0], %1, 0x989680;\n\t"
        "@P bra DONE_%=;\n\t"
        "bra WAIT_%=;\n\t"
        "DONE_%=:\n\t"
        "}"
        :: "r"(mb), "r"(parity) : "memory");
}

__device__ __forceinline__ void mbar_arrive(unsigned int mb) {
    asm volatile("mbarrier.arrive.release.cta.shared::cta.b64 _, [%0];"
                 :: "r"(mb) : "memory");
}

__device__ __forceinline__ void tma_issue(unsigned int mb, unsigned int dst,
                                          const float* src) {
    asm volatile("mbarrier.arrive.expect_tx.shared.b64 _, [%0], %1;"
                 :: "r"(mb), "r"((unsigned int)CHUNK_BYTES) : "memory");
    asm volatile("cp.async.bulk.shared::cluster.global.mbarrier::complete_tx::bytes "
                 "[%0], [%1], %2, [%3];"
                 :: "r"(dst), "l"(src), "r"((unsigned int)CHUNK_BYTES), "r"(mb)
                 : "memory");
}

// exp(x + EPS) = exp2(x*log2e + EPS*log2e): one FFMA + one MUFU.EX2
__device__ __forceinline__ float expe(float x) {
    return exp2f(fmaf(x, LOG2E, EPS * LOG2E));
}

__global__ __launch_bounds__(NT, 2)
void smsoftmax_kernel(const float* __restrict__ logits,
                      const float* __restrict__ dist,
                      float* __restrict__ out, int B) {
    extern __shared__ float4 buf[];              // NBUF x CHUNK_F4 float4 = 96000 B
    __shared__ __align__(8) unsigned long long mbar_full[NBUF];
    __shared__ __align__(8) unsigned long long mbar_empty[NBUF];
    __shared__ float red[2][16];                 // double-buffered by row parity
    __shared__ int   sh_next[2];

    const int tid  = threadIdx.x;
    const int lane = tid & 31;
    const int wid  = tid >> 5;

    const unsigned int fb_base  = smem_u32(&mbar_full[0]);   // +8*i
    const unsigned int eb_base  = smem_u32(&mbar_empty[0]);  // +8*i
    const unsigned int dst_base = smem_u32(buf);             // +i*CHUNK_BYTES

    if (tid == 0) {
        #pragma unroll
        for (int i = 0; i < NBUF; i++) {
            asm volatile("mbarrier.init.shared.b64 [%0], 1;"
                         :: "r"(fb_base + 8u * i) : "memory");
            asm volatile("mbarrier.init.shared.b64 [%0], %1;"
                         :: "r"(eb_base + 8u * i), "r"(NT) : "memory");
        }
    }
    __syncthreads();

    int cur = blockIdx.x;                        // static seed: rows 0..GRID-1

    // Prologue: prime the 6 buffers with chunks 0..5 of cur.
    if (tid == 0 && cur < B) {
        const float* base = logits + (size_t)cur * C_DIM;
        #pragma unroll
        for (int i = 0; i < NBUF; i++)
            tma_issue(fb_base + 8u * i, dst_base + (unsigned int)i * CHUNK_BYTES,
                      base + (size_t)i * CHUNK_F);
    }

    const float c   = __expf(-__ldg(dist));
    const float cm1 = c - 1.0f;

    unsigned int pmask = 0;                      // full-barrier parity (all threads)
    unsigned int emask = 0;                      // empty-barrier parity (tid0 only)
    int sb = 0;                                  // starting buffer of current row
    int rp = 0;                                  // row parity for red/sh_next slots

    __half2 eh[32];                              // fp16 e for one full row (regs)

    while (cur < B) {
        float s = 0.0f;
        int nxt = B;

        #pragma unroll
        for (int cslot = 0; cslot < NCH; cslot++) {
            int b = sb + cslot;                  // runtime buffer index, 0..11
            if (b >= NBUF) b -= NBUF;
            if (b >= NBUF) b -= NBUF;            // sb<=5, cslot<=7 -> at most 2 wraps
            const unsigned int fba = fb_base + 8u * (unsigned int)b;
            const unsigned int eba = eb_base + 8u * (unsigned int)b;

            mbar_wait(fba, (pmask >> b) & 1u);
            pmask ^= (1u << b);

            const float4* __restrict__ cb = buf + b * CHUNK_F4;
            #pragma unroll
            for (int j = 0; j < 2; j++) {
                int idx = j * NT + tid;
                if (idx < CHUNK_F4) {
                    float4 t = cb[idx];
                    float ex = expe(t.x), ey = expe(t.y);
                    float ez = expe(t.z), ew = expe(t.w);
                    s += (ex + ey) + (ez + ew);
                    eh[cslot * 4 + j * 2]     = __floats2half2_rn(ex, ey);
                    eh[cslot * 4 + j * 2 + 1] = __floats2half2_rn(ez, ew);
                }
            }
            // per-thread consumer release: my reads of buffer b are done
            mbar_arrive(eba);

            if (tid == 0) {
                if (cslot == 0) {
                    nxt = atomicAdd(&g_ctr, 1);  // latency hidden by later drains
                    sh_next[rp] = nxt;
                }
                // refill same buffer with chunk q+6:
                //   cslots 0,1 -> chunks 6,7 of cur; cslots 2..7 -> chunks 0..5 of nxt
                const int trow = (cslot < 2) ? cur : nxt;
                const int tch  = (cslot < 2) ? (cslot + 6) : (cslot - 2);
                if (trow < B) {
                    mbar_wait(eba, (emask >> b) & 1u);   // all 512 drained b
                    emask ^= (1u << b);
                    const float* src = logits + (size_t)trow * C_DIM
                                              + (size_t)tch * CHUNK_F;
                    tma_issue(fba, dst_base + (unsigned int)b * CHUNK_BYTES, src);
                }
            }
        }
        sb += 2;                                 // 8 chunks advance start by 8%6 = 2
        if (sb >= NBUF) sb -= NBUF;

        // ---- reduce: warp partials -> ONE barrier -> redundant final fold ----
        float rr = s;
        #pragma unroll
        for (int o = 16; o > 0; o >>= 1)
            rr += __shfl_xor_sync(0xffffffffu, rr, o);
        if (lane == 0) red[rp][wid] = rr;
        __syncthreads();                         // the only block barrier per row

        float t = red[rp][lane & 15];            // every warp folds all 16 partials
        #pragma unroll
        for (int o = 8; o > 0; o >>= 1)
            t += __shfl_xor_sync(0xffffffffu, t, o);

        const int nxtrow = sh_next[rp];          // ordered by the barrier above

        // Per-row scalars: r0 = 1/(s+EPS); out = (c*r0*e) * (1 - cm1*r0*e)
        const float r0 = __fdividef(1.0f, t + EPS);
        const float a  = c * r0;
        const float bb = cm1 * r0;

        // ---- epilogue: pure FMA + STG (overlaps in-flight next-row chunks) ----
        float4* __restrict__ out4 = (float4*)(out + (size_t)cur * C_DIM);
        #pragma unroll
        for (int cs = 0; cs < NCH; cs++) {
            #pragma unroll
            for (int j = 0; j < 2; j++) {
                int idx = j * NT + tid;
                if (idx < CHUNK_F4) {
                    float2 lo = __half22float2(eh[cs * 4 + j * 2]);
                    float2 hi = __half22float2(eh[cs * 4 + j * 2 + 1]);
                    float4 o;
                    o.x = (a * lo.x) * fmaf(-bb, lo.x, 1.0f);
                    o.y = (a * lo.y) * fmaf(-bb, lo.y, 1.0f);
                    o.z = (a * hi.x) * fmaf(-bb, hi.x, 1.0f);
                    o.w = (a * hi.y) * fmaf(-bb, hi.y, 1.0f);
                    out4[cs * CHUNK_F4 + idx] = o;
                }
            }
        }

        cur = nxtrow;
        rp ^= 1;                                 // flip red/sh_next slot
    }

    // ---- self-reset for the next launch: last CTA out restores the queue ----
    __syncthreads();                             // all this CTA's g_ctr use is done
    if (tid == 0) {
        const int d = atomicAdd(&g_done, 1);
        if (d == GRID - 1) {                     // I am the last CTA to exit
            atomicExch(&g_ctr, GRID);
            atomicExch(&g_done, 0);
        }
    }
}

extern "C" void kernel_launch(void* const* d_in, const int* in_sizes, int n_in,
                              void* d_out, int out_size) {
    const float* logits = (const float*)d_in[0];
    const float* dist   = (const float*)d_in[1];
    float* out = (float*)d_out;

    const int B = in_sizes[0] / C_DIM;                 // 4096 rows
    const size_t smem = (size_t)NBUF * CHUNK_BYTES;    // 96000 B per CTA

    cudaFuncSetAttribute(smsoftmax_kernel,
                         cudaFuncAttributeMaxDynamicSharedMemorySize, (int)smem);
    smsoftmax_kernel<<<GRID, NT, smem>>>(logits, dist, out, B);
}